// round 1
// baseline (speedup 1.0000x reference)
#include <cuda_runtime.h>
#include <cuda_bf16.h>

#define N_NODES 100000
#define N_EDGES 3200000
#define DIM 64
#define N_LAYERS 3
#define OUT_DIM (4 * DIM)

// Scratch (allocation-free contract: __device__ globals)
__device__ float g_hn[N_NODES * DIM];        // aggregated neighbor messages
__device__ float g_h[2][N_NODES * DIM];      // compact h double-buffer

// ---------------------------------------------------------------------------
// Zero h_n (float4-vectorized, grid-stride)
// ---------------------------------------------------------------------------
__global__ void zero_kernel(float4* __restrict__ p, int n4) {
    int i = blockIdx.x * blockDim.x + threadIdx.x;
    const float4 z = make_float4(0.f, 0.f, 0.f, 0.f);
    for (; i < n4; i += gridDim.x * blockDim.x) p[i] = z;
}

// ---------------------------------------------------------------------------
// Copy x into out[:, 0:64] (first concat segment)
// ---------------------------------------------------------------------------
__global__ void copy_x_kernel(const float4* __restrict__ x4, float4* __restrict__ out4) {
    int i = blockIdx.x * blockDim.x + threadIdx.x;          // over N*16 float4s
    if (i >= N_NODES * (DIM / 4)) return;
    int n = i >> 4;                                          // node
    int c = i & 15;                                          // float4 col within dim
    out4[n * (OUT_DIM / 4) + c] = x4[i];
}

// ---------------------------------------------------------------------------
// Edge scatter: h_n[dst] += a_e * h[src]
// 16 lanes per edge, one float4 per lane, vector red.global.add.v4.f32
// ---------------------------------------------------------------------------
__global__ void scatter_kernel(const float4* __restrict__ h4,
                               const float*  __restrict__ a,
                               const int*    __restrict__ src,
                               const int*    __restrict__ dst,
                               float4*       __restrict__ hn4) {
    long long t = (long long)blockIdx.x * blockDim.x + threadIdx.x;
    int e = (int)(t >> 4);
    int lane = (int)(t & 15);
    if (e >= N_EDGES) return;
    int s = src[e];
    int d = dst[e];
    float ae = a[e];
    float4 v = h4[s * 16 + lane];
    v.x *= ae; v.y *= ae; v.z *= ae; v.w *= ae;
    float4* addr = hn4 + d * 16 + lane;
    asm volatile("red.global.add.v4.f32 [%0], {%1,%2,%3,%4};"
                 :: "l"(addr), "f"(v.x), "f"(v.y), "f"(v.z), "f"(v.w)
                 : "memory");
}

// ---------------------------------------------------------------------------
// Node update: h_out = lrelu((h+h_n)@W1 + b1) + lrelu((h*h_n)@W2 + b2)
// Block = 256 threads, processes NPB nodes; W1,W2 cached in shared.
// Thread layout per group: nodeSub = t>>6 (4 nodes), col = t&63.
// ---------------------------------------------------------------------------
#define NPB 64

__global__ __launch_bounds__(256)
void update_kernel(const float* __restrict__ h,
                   const float* __restrict__ hn,
                   const float* __restrict__ W1,
                   const float* __restrict__ b1,
                   const float* __restrict__ W2,
                   const float* __restrict__ b2,
                   float* __restrict__ hout,       // compact [N,64]
                   float* __restrict__ outSeg) {   // out + 64*(l+1), row stride 256
    __shared__ float sW1[DIM * DIM];
    __shared__ float sW2[DIM * DIM];
    __shared__ float sb1[DIM];
    __shared__ float sb2[DIM];
    __shared__ float ss[4][DIM];
    __shared__ float sp[4][DIM];

    int t = threadIdx.x;

    // Load weights into shared (float4 vectorized: 4096 floats = 1024 float4 each)
    {
        const float4* w1v = (const float4*)W1;
        const float4* w2v = (const float4*)W2;
        float4* s1v = (float4*)sW1;
        float4* s2v = (float4*)sW2;
        #pragma unroll
        for (int i = 0; i < 4; i++) {
            s1v[t + i * 256] = w1v[t + i * 256];
            s2v[t + i * 256] = w2v[t + i * 256];
        }
        if (t < DIM) { sb1[t] = b1[t]; sb2[t] = b2[t]; }
    }
    __syncthreads();

    int base = blockIdx.x * NPB;
    int nodeSub = t >> 6;   // 0..3
    int col = t & 63;

    for (int g = 0; g < NPB / 4; g++) {
        int node = base + g * 4 + nodeSub;
        // stage s = h + hn, p = h * hn  (each thread loads one element)
        if (node < N_NODES) {
            int idx = node * DIM + col;
            float hv = h[idx];
            float hnv = hn[idx];
            ss[nodeSub][col] = hv + hnv;
            sp[nodeSub][col] = hv * hnv;
        }
        __syncthreads();

        if (node < N_NODES) {
            float acc1 = sb1[col];
            float acc2 = sb2[col];
            #pragma unroll
            for (int k = 0; k < DIM; k++) {
                acc1 = fmaf(ss[nodeSub][k], sW1[k * DIM + col], acc1);
                acc2 = fmaf(sp[nodeSub][k], sW2[k * DIM + col], acc2);
            }
            float r1 = acc1 > 0.f ? acc1 : 0.01f * acc1;
            float r2 = acc2 > 0.f ? acc2 : 0.01f * acc2;
            float r = r1 + r2;
            hout[node * DIM + col] = r;
            outSeg[node * OUT_DIM + col] = r;
        }
        __syncthreads();
    }
}

// ---------------------------------------------------------------------------
// Launch
// Inputs: x[N,64], a[E], W1s[3,64,64], b1s[3,64], W2s[3,64,64], b2s[3,64],
//         src[E], dst[E].  Output: [N, 256] fp32
// ---------------------------------------------------------------------------
extern "C" void kernel_launch(void* const* d_in, const int* in_sizes, int n_in,
                              void* d_out, int out_size) {
    const float* x   = (const float*)d_in[0];
    const float* a   = (const float*)d_in[1];
    const float* W1s = (const float*)d_in[2];
    const float* b1s = (const float*)d_in[3];
    const float* W2s = (const float*)d_in[4];
    const float* b2s = (const float*)d_in[5];
    const int*   src = (const int*)d_in[6];
    const int*   dst = (const int*)d_in[7];
    float* out = (float*)d_out;

    float* hn;
    float* hbuf0;
    float* hbuf1;
    cudaGetSymbolAddress((void**)&hn, g_hn);
    cudaGetSymbolAddress((void**)&hbuf0, g_h);
    hbuf1 = hbuf0 + (size_t)N_NODES * DIM;

    const int ZERO_N4 = N_NODES * DIM / 4;
    const int ZERO_BLOCKS = 2048;

    // out[:, 0:64] = x
    {
        int n4 = N_NODES * (DIM / 4);
        copy_x_kernel<<<(n4 + 255) / 256, 256>>>((const float4*)x, (float4*)out);
    }

    const float* hin = x;
    float* houts[3] = {hbuf0, hbuf1, hbuf0};

    long long scat_threads = (long long)N_EDGES * 16;
    int scat_blocks = (int)((scat_threads + 255) / 256);

    for (int l = 0; l < N_LAYERS; l++) {
        zero_kernel<<<ZERO_BLOCKS, 256>>>((float4*)hn, ZERO_N4);
        scatter_kernel<<<scat_blocks, 256>>>((const float4*)hin, a, src, dst, (float4*)hn);
        update_kernel<<<(N_NODES + NPB - 1) / NPB, 256>>>(
            hin, hn,
            W1s + (size_t)l * DIM * DIM, b1s + (size_t)l * DIM,
            W2s + (size_t)l * DIM * DIM, b2s + (size_t)l * DIM,
            houts[l], out + (size_t)(l + 1) * DIM);
        hin = houts[l];
    }
}

// round 2
// speedup vs baseline: 1.3425x; 1.3425x over previous
#include <cuda_runtime.h>
#include <cuda_bf16.h>

#define N_NODES 100000
#define N_EDGES 3200000
#define DIM 64
#define N_LAYERS 3
#define OUT_DIM (4 * DIM)

// Scratch (allocation-free contract: __device__ globals)
__device__ float g_hn[N_NODES * DIM];        // aggregated neighbor messages
__device__ float g_h[2][N_NODES * DIM];      // compact h double-buffer

// ---------------------------------------------------------------------------
// Zero h_n (float4-vectorized, grid-stride)
// ---------------------------------------------------------------------------
__global__ void zero_kernel(float4* __restrict__ p, int n4) {
    int i = blockIdx.x * blockDim.x + threadIdx.x;
    const float4 z = make_float4(0.f, 0.f, 0.f, 0.f);
    for (; i < n4; i += gridDim.x * blockDim.x) p[i] = z;
}

// ---------------------------------------------------------------------------
// Copy x into out[:, 0:64] (first concat segment)
// ---------------------------------------------------------------------------
__global__ void copy_x_kernel(const float4* __restrict__ x4, float4* __restrict__ out4) {
    int i = blockIdx.x * blockDim.x + threadIdx.x;          // over N*16 float4s
    if (i >= N_NODES * (DIM / 4)) return;
    int n = i >> 4;                                          // node
    int c = i & 15;                                          // float4 col within dim
    out4[n * (OUT_DIM / 4) + c] = x4[i];
}

// ---------------------------------------------------------------------------
// Edge scatter: h_n[dst] += a_e * h[src]
// 16 lanes per edge, one float4 per lane, vector red.global.add.v4.f32
// ---------------------------------------------------------------------------
__global__ void scatter_kernel(const float4* __restrict__ h4,
                               const float*  __restrict__ a,
                               const int*    __restrict__ src,
                               const int*    __restrict__ dst,
                               float4*       __restrict__ hn4) {
    long long t = (long long)blockIdx.x * blockDim.x + threadIdx.x;
    int e = (int)(t >> 4);
    int lane = (int)(t & 15);
    if (e >= N_EDGES) return;
    int s = src[e];
    int d = dst[e];
    float ae = a[e];
    float4 v = h4[s * 16 + lane];
    v.x *= ae; v.y *= ae; v.z *= ae; v.w *= ae;
    float4* addr = hn4 + d * 16 + lane;
    asm volatile("red.global.add.v4.f32 [%0], {%1,%2,%3,%4};"
                 :: "l"(addr), "f"(v.x), "f"(v.y), "f"(v.z), "f"(v.w)
                 : "memory");
}

// ---------------------------------------------------------------------------
// Node update (register-tiled):
//   h_out = lrelu((h+h_n)@W1 + b1) + lrelu((h*h_n)@W2 + b2)
// Block = 256 threads, tile = 64 nodes x 64 cols.
// Each thread computes 4 nodes x 4 cols for BOTH matrices (32 accumulators).
// s,p staged TRANSPOSED in shared: sS[k][node] (row stride 68 floats).
// ---------------------------------------------------------------------------
#define SPAD 68   // 64 + 4 pad: odd bank stride for staging stores, 16B-aligned rows

__device__ __forceinline__ float lrelu(float v) {
    return v > 0.f ? v : 0.01f * v;
}

extern __shared__ float dyn_smem[];

__global__ __launch_bounds__(256)
void update_kernel(const float* __restrict__ h,
                   const float* __restrict__ hn,
                   const float* __restrict__ W1,
                   const float* __restrict__ b1,
                   const float* __restrict__ W2,
                   const float* __restrict__ b2,
                   float* __restrict__ hout,       // compact [N,64]
                   float* __restrict__ outSeg) {   // out + 64*(l+1), row stride 256
    float* sW1 = dyn_smem;                 // [64*64]
    float* sW2 = sW1 + DIM * DIM;          // [64*64]
    float* sS  = sW2 + DIM * DIM;          // [64][SPAD]  (k-major, transposed)
    float* sP  = sS + DIM * SPAD;          // [64][SPAD]

    int t = threadIdx.x;

    // Load weights into shared (float4 vectorized: 4096 floats = 1024 float4 each)
    {
        const float4* w1v = (const float4*)W1;
        const float4* w2v = (const float4*)W2;
        float4* s1v = (float4*)sW1;
        float4* s2v = (float4*)sW2;
        #pragma unroll
        for (int i = 0; i < 4; i++) {
            s1v[t + i * 256] = w1v[t + i * 256];
            s2v[t + i * 256] = w2v[t + i * 256];
        }
    }

    int base = blockIdx.x * 64;

    // ---- Stage s = h + hn, p = h * hn, transposed to [k][node] ----
    {
        int nloc = t & 63;
        int cgBase = t >> 6;                 // 0..3
        int node = base + nloc;
        bool valid = node < N_NODES;
        const float4* hrow  = (const float4*)h  + (size_t)node * 16;
        const float4* hnrow = (const float4*)hn + (size_t)node * 16;
        #pragma unroll
        for (int j = 0; j < 4; j++) {
            int cg = cgBase + 4 * j;         // float4-column group 0..15
            float4 hv, hnv;
            if (valid) { hv = hrow[cg]; hnv = hnrow[cg]; }
            else { hv = make_float4(0.f,0.f,0.f,0.f); hnv = hv; }
            int k0 = cg * 4;
            sS[(k0 + 0) * SPAD + nloc] = hv.x + hnv.x;
            sS[(k0 + 1) * SPAD + nloc] = hv.y + hnv.y;
            sS[(k0 + 2) * SPAD + nloc] = hv.z + hnv.z;
            sS[(k0 + 3) * SPAD + nloc] = hv.w + hnv.w;
            sP[(k0 + 0) * SPAD + nloc] = hv.x * hnv.x;
            sP[(k0 + 1) * SPAD + nloc] = hv.y * hnv.y;
            sP[(k0 + 2) * SPAD + nloc] = hv.z * hnv.z;
            sP[(k0 + 3) * SPAD + nloc] = hv.w * hnv.w;
        }
    }
    __syncthreads();

    // ---- Register-tiled GEMM: 4 nodes x 4 cols per thread, both matrices ----
    int m0 = (t & 15) * 4;     // node offset within tile
    int c0 = (t >> 4) * 4;     // col offset

    float acc1[4][4];
    float acc2[4][4];
    #pragma unroll
    for (int i = 0; i < 4; i++)
        #pragma unroll
        for (int j = 0; j < 4; j++) { acc1[i][j] = 0.f; acc2[i][j] = 0.f; }

    #pragma unroll 4
    for (int k = 0; k < DIM; k++) {
        float4 sv = *(const float4*)(sS + k * SPAD + m0);
        float4 pv = *(const float4*)(sP + k * SPAD + m0);
        float4 w1 = *(const float4*)(sW1 + k * DIM + c0);
        float4 w2 = *(const float4*)(sW2 + k * DIM + c0);
        float sm[4] = {sv.x, sv.y, sv.z, sv.w};
        float pm[4] = {pv.x, pv.y, pv.z, pv.w};
        float w1a[4] = {w1.x, w1.y, w1.z, w1.w};
        float w2a[4] = {w2.x, w2.y, w2.z, w2.w};
        #pragma unroll
        for (int i = 0; i < 4; i++) {
            #pragma unroll
            for (int j = 0; j < 4; j++) {
                acc1[i][j] = fmaf(sm[i], w1a[j], acc1[i][j]);
                acc2[i][j] = fmaf(pm[i], w2a[j], acc2[i][j]);
            }
        }
    }

    // ---- Epilogue: bias, leaky-relu, sum, store ----
    float4 rb1 = *(const float4*)(b1 + c0);
    float4 rb2 = *(const float4*)(b2 + c0);
    float b1a[4] = {rb1.x, rb1.y, rb1.z, rb1.w};
    float b2a[4] = {rb2.x, rb2.y, rb2.z, rb2.w};

    #pragma unroll
    for (int i = 0; i < 4; i++) {
        int node = base + m0 + i;
        if (node >= N_NODES) break;
        float4 r;
        float* rp = (float*)&r;
        #pragma unroll
        for (int j = 0; j < 4; j++)
            rp[j] = lrelu(acc1[i][j] + b1a[j]) + lrelu(acc2[i][j] + b2a[j]);
        *(float4*)(hout + (size_t)node * DIM + c0) = r;
        *(float4*)(outSeg + (size_t)node * OUT_DIM + c0) = r;
    }
}

// ---------------------------------------------------------------------------
// Launch
// ---------------------------------------------------------------------------
extern "C" void kernel_launch(void* const* d_in, const int* in_sizes, int n_in,
                              void* d_out, int out_size) {
    const float* x   = (const float*)d_in[0];
    const float* a   = (const float*)d_in[1];
    const float* W1s = (const float*)d_in[2];
    const float* b1s = (const float*)d_in[3];
    const float* W2s = (const float*)d_in[4];
    const float* b2s = (const float*)d_in[5];
    const int*   src = (const int*)d_in[6];
    const int*   dst = (const int*)d_in[7];
    float* out = (float*)d_out;

    float* hn;
    float* hbuf0;
    float* hbuf1;
    cudaGetSymbolAddress((void**)&hn, g_hn);
    cudaGetSymbolAddress((void**)&hbuf0, g_h);
    hbuf1 = hbuf0 + (size_t)N_NODES * DIM;

    const int ZERO_N4 = N_NODES * DIM / 4;
    const int ZERO_BLOCKS = 2048;

    const int UPD_SMEM = (2 * DIM * DIM + 2 * DIM * SPAD) * (int)sizeof(float); // 67584
    cudaFuncSetAttribute(update_kernel, cudaFuncAttributeMaxDynamicSharedMemorySize, UPD_SMEM);

    // out[:, 0:64] = x
    {
        int n4 = N_NODES * (DIM / 4);
        copy_x_kernel<<<(n4 + 255) / 256, 256>>>((const float4*)x, (float4*)out);
    }

    const float* hin = x;
    float* houts[3] = {hbuf0, hbuf1, hbuf0};

    long long scat_threads = (long long)N_EDGES * 16;
    int scat_blocks = (int)((scat_threads + 255) / 256);

    for (int l = 0; l < N_LAYERS; l++) {
        zero_kernel<<<ZERO_BLOCKS, 256>>>((float4*)hn, ZERO_N4);
        scatter_kernel<<<scat_blocks, 256>>>((const float4*)hin, a, src, dst, (float4*)hn);
        update_kernel<<<(N_NODES + 63) / 64, 256, UPD_SMEM>>>(
            hin, hn,
            W1s + (size_t)l * DIM * DIM, b1s + (size_t)l * DIM,
            W2s + (size_t)l * DIM * DIM, b2s + (size_t)l * DIM,
            houts[l], out + (size_t)(l + 1) * DIM);
        hin = houts[l];
    }
}

// round 3
// speedup vs baseline: 2.0570x; 1.5322x over previous
#include <cuda_runtime.h>
#include <cuda_bf16.h>

#define N_NODES 100000
#define N_EDGES 3200000
#define DIM 64
#define N_LAYERS 3
#define OUT_DIM (4 * DIM)

#define SCAN_B 1024
#define SCAN_NBLK ((N_NODES + SCAN_B - 1) / SCAN_B)   // 98
#define CHUNK 64                                       // sorted edges per half-warp

// ---------------------------------------------------------------------------
// Scratch (allocation-free contract: __device__ globals)
// ---------------------------------------------------------------------------
__device__ float g_hn[N_NODES * DIM];        // aggregated neighbor messages
__device__ float g_h[2][N_NODES * DIM];      // compact h double-buffer
__device__ int   g_count[N_NODES];           // per-dst degree histogram
__device__ int   g_cursor[N_NODES];          // exclusive offsets -> running cursor
__device__ int   g_blocksums[128];           // scan block sums
__device__ int4  g_sorted[N_EDGES];          // packed {src, dst, a_bits, 0}, dst-sorted

// ---------------------------------------------------------------------------
// Generic zero (float4-vectorized, grid-stride)
// ---------------------------------------------------------------------------
__global__ void zero_kernel(float4* __restrict__ p, int n4) {
    int i = blockIdx.x * blockDim.x + threadIdx.x;
    const float4 z = make_float4(0.f, 0.f, 0.f, 0.f);
    for (; i < n4; i += gridDim.x * blockDim.x) p[i] = z;
}

// ---------------------------------------------------------------------------
// Copy x into out[:, 0:64]
// ---------------------------------------------------------------------------
__global__ void copy_x_kernel(const float4* __restrict__ x4, float4* __restrict__ out4) {
    int i = blockIdx.x * blockDim.x + threadIdx.x;
    if (i >= N_NODES * (DIM / 4)) return;
    int n = i >> 4;
    int c = i & 15;
    out4[n * (OUT_DIM / 4) + c] = x4[i];
}

// ---------------------------------------------------------------------------
// Counting sort by dst: histogram
// ---------------------------------------------------------------------------
__global__ void hist_kernel(const int* __restrict__ dst) {
    int e = blockIdx.x * blockDim.x + threadIdx.x;
    if (e >= N_EDGES) return;
    atomicAdd(&g_count[dst[e]], 1);
}

// Scan K1: per-block totals of g_count
__global__ __launch_bounds__(SCAN_B)
void scan_sum_kernel() {
    int i = blockIdx.x * SCAN_B + threadIdx.x;
    int v = (i < N_NODES) ? g_count[i] : 0;
    int lane = threadIdx.x & 31, w = threadIdx.x >> 5;
    #pragma unroll
    for (int d = 16; d; d >>= 1) v += __shfl_down_sync(~0u, v, d);
    __shared__ int s[32];
    if (lane == 0) s[w] = v;
    __syncthreads();
    if (w == 0) {
        v = s[lane];
        #pragma unroll
        for (int d = 16; d; d >>= 1) v += __shfl_down_sync(~0u, v, d);
        if (lane == 0) g_blocksums[blockIdx.x] = v;
    }
}

// Scan K2: exclusive scan of SCAN_NBLK block totals (single block)
__global__ void scan_tops_kernel() {
    __shared__ int s[128];
    int tid = threadIdx.x;
    int v = (tid < SCAN_NBLK) ? g_blocksums[tid] : 0;
    s[tid] = v;
    __syncthreads();
    for (int off = 1; off < 128; off <<= 1) {
        int t = (tid >= off) ? s[tid - off] : 0;
        __syncthreads();
        s[tid] += t;
        __syncthreads();
    }
    if (tid < SCAN_NBLK) g_blocksums[tid] = s[tid] - v;   // exclusive
}

// Scan K3: per-block exclusive scan + block offset -> g_cursor
__global__ __launch_bounds__(SCAN_B)
void scan_write_kernel() {
    int i = blockIdx.x * SCAN_B + threadIdx.x;
    int v = (i < N_NODES) ? g_count[i] : 0;
    int lane = threadIdx.x & 31, w = threadIdx.x >> 5;
    int inc = v;
    #pragma unroll
    for (int d = 1; d < 32; d <<= 1) {
        int t = __shfl_up_sync(~0u, inc, d);
        if (lane >= d) inc += t;
    }
    __shared__ int ws[32];
    if (lane == 31) ws[w] = inc;
    __syncthreads();
    if (w == 0) {
        int t = ws[lane];
        #pragma unroll
        for (int d = 1; d < 32; d <<= 1) {
            int u = __shfl_up_sync(~0u, t, d);
            if (lane >= d) t += u;
        }
        ws[lane] = t;   // inclusive scan of warp sums
    }
    __syncthreads();
    int warpOff = (w == 0) ? 0 : ws[w - 1];
    int excl = inc - v + warpOff + g_blocksums[blockIdx.x];
    if (i < N_NODES) g_cursor[i] = excl;
}

// Reorder: place packed edge records in dst order
__global__ void reorder_kernel(const int* __restrict__ src,
                               const int* __restrict__ dst,
                               const float* __restrict__ a) {
    int e = blockIdx.x * blockDim.x + threadIdx.x;
    if (e >= N_EDGES) return;
    int d = dst[e];
    int pos = atomicAdd(&g_cursor[d], 1);
    int4 rec;
    rec.x = src[e];
    rec.y = d;
    rec.z = __float_as_int(a[e]);
    rec.w = 0;
    g_sorted[pos] = rec;
}

// ---------------------------------------------------------------------------
// Segment aggregation over dst-sorted edges.
// Half-warp (16 lanes = one 64-float row) walks CHUNK consecutive edges,
// accumulates per-dst in registers, red.v4 flush on dst change / chunk end.
// ---------------------------------------------------------------------------
__device__ __forceinline__ void red_v4(float4* addr, float4 v) {
    asm volatile("red.global.add.v4.f32 [%0], {%1,%2,%3,%4};"
                 :: "l"(addr), "f"(v.x), "f"(v.y), "f"(v.z), "f"(v.w)
                 : "memory");
}

__global__ __launch_bounds__(256)
void agg_kernel(const float4* __restrict__ h4, float4* __restrict__ hn4) {
    int hw = (blockIdx.x * blockDim.x + threadIdx.x) >> 4;
    int lane = threadIdx.x & 15;
    long long start = (long long)hw * CHUNK;
    if (start >= N_EDGES) return;
    const int4* ep = g_sorted + start;

    float4 acc = make_float4(0.f, 0.f, 0.f, 0.f);
    int cur = ep[0].y;

    #pragma unroll 4
    for (int j = 0; j < CHUNK; j++) {
        int4 r = ep[j];
        if (r.y != cur) {
            red_v4(hn4 + (size_t)cur * 16 + lane, acc);
            acc = make_float4(0.f, 0.f, 0.f, 0.f);
            cur = r.y;
        }
        float ae = __int_as_float(r.z);
        float4 v = h4[(size_t)r.x * 16 + lane];
        acc.x = fmaf(ae, v.x, acc.x);
        acc.y = fmaf(ae, v.y, acc.y);
        acc.z = fmaf(ae, v.z, acc.z);
        acc.w = fmaf(ae, v.w, acc.w);
    }
    red_v4(hn4 + (size_t)cur * 16 + lane, acc);
}

// ---------------------------------------------------------------------------
// Node update (register-tiled, unchanged from R2):
//   h_out = lrelu((h+h_n)@W1 + b1) + lrelu((h*h_n)@W2 + b2)
// ---------------------------------------------------------------------------
#define SPAD 68

__device__ __forceinline__ float lrelu(float v) {
    return v > 0.f ? v : 0.01f * v;
}

extern __shared__ float dyn_smem[];

__global__ __launch_bounds__(256)
void update_kernel(const float* __restrict__ h,
                   const float* __restrict__ hn,
                   const float* __restrict__ W1,
                   const float* __restrict__ b1,
                   const float* __restrict__ W2,
                   const float* __restrict__ b2,
                   float* __restrict__ hout,
                   float* __restrict__ outSeg) {
    float* sW1 = dyn_smem;
    float* sW2 = sW1 + DIM * DIM;
    float* sS  = sW2 + DIM * DIM;
    float* sP  = sS + DIM * SPAD;

    int t = threadIdx.x;

    {
        const float4* w1v = (const float4*)W1;
        const float4* w2v = (const float4*)W2;
        float4* s1v = (float4*)sW1;
        float4* s2v = (float4*)sW2;
        #pragma unroll
        for (int i = 0; i < 4; i++) {
            s1v[t + i * 256] = w1v[t + i * 256];
            s2v[t + i * 256] = w2v[t + i * 256];
        }
    }

    int base = blockIdx.x * 64;

    {
        int nloc = t & 63;
        int cgBase = t >> 6;
        int node = base + nloc;
        bool valid = node < N_NODES;
        const float4* hrow  = (const float4*)h  + (size_t)node * 16;
        const float4* hnrow = (const float4*)hn + (size_t)node * 16;
        #pragma unroll
        for (int j = 0; j < 4; j++) {
            int cg = cgBase + 4 * j;
            float4 hv, hnv;
            if (valid) { hv = hrow[cg]; hnv = hnrow[cg]; }
            else { hv = make_float4(0.f,0.f,0.f,0.f); hnv = hv; }
            int k0 = cg * 4;
            sS[(k0 + 0) * SPAD + nloc] = hv.x + hnv.x;
            sS[(k0 + 1) * SPAD + nloc] = hv.y + hnv.y;
            sS[(k0 + 2) * SPAD + nloc] = hv.z + hnv.z;
            sS[(k0 + 3) * SPAD + nloc] = hv.w + hnv.w;
            sP[(k0 + 0) * SPAD + nloc] = hv.x * hnv.x;
            sP[(k0 + 1) * SPAD + nloc] = hv.y * hnv.y;
            sP[(k0 + 2) * SPAD + nloc] = hv.z * hnv.z;
            sP[(k0 + 3) * SPAD + nloc] = hv.w * hnv.w;
        }
    }
    __syncthreads();

    int m0 = (t & 15) * 4;
    int c0 = (t >> 4) * 4;

    float acc1[4][4];
    float acc2[4][4];
    #pragma unroll
    for (int i = 0; i < 4; i++)
        #pragma unroll
        for (int j = 0; j < 4; j++) { acc1[i][j] = 0.f; acc2[i][j] = 0.f; }

    #pragma unroll 4
    for (int k = 0; k < DIM; k++) {
        float4 sv = *(const float4*)(sS + k * SPAD + m0);
        float4 pv = *(const float4*)(sP + k * SPAD + m0);
        float4 w1 = *(const float4*)(sW1 + k * DIM + c0);
        float4 w2 = *(const float4*)(sW2 + k * DIM + c0);
        float sm[4] = {sv.x, sv.y, sv.z, sv.w};
        float pm[4] = {pv.x, pv.y, pv.z, pv.w};
        float w1a[4] = {w1.x, w1.y, w1.z, w1.w};
        float w2a[4] = {w2.x, w2.y, w2.z, w2.w};
        #pragma unroll
        for (int i = 0; i < 4; i++) {
            #pragma unroll
            for (int j = 0; j < 4; j++) {
                acc1[i][j] = fmaf(sm[i], w1a[j], acc1[i][j]);
                acc2[i][j] = fmaf(pm[i], w2a[j], acc2[i][j]);
            }
        }
    }

    float4 rb1 = *(const float4*)(b1 + c0);
    float4 rb2 = *(const float4*)(b2 + c0);
    float b1a[4] = {rb1.x, rb1.y, rb1.z, rb1.w};
    float b2a[4] = {rb2.x, rb2.y, rb2.z, rb2.w};

    #pragma unroll
    for (int i = 0; i < 4; i++) {
        int node = base + m0 + i;
        if (node >= N_NODES) break;
        float4 r;
        float* rp = (float*)&r;
        #pragma unroll
        for (int j = 0; j < 4; j++)
            rp[j] = lrelu(acc1[i][j] + b1a[j]) + lrelu(acc2[i][j] + b2a[j]);
        *(float4*)(hout + (size_t)node * DIM + c0) = r;
        *(float4*)(outSeg + (size_t)node * OUT_DIM + c0) = r;
    }
}

// ---------------------------------------------------------------------------
// Launch
// ---------------------------------------------------------------------------
extern "C" void kernel_launch(void* const* d_in, const int* in_sizes, int n_in,
                              void* d_out, int out_size) {
    const float* x   = (const float*)d_in[0];
    const float* a   = (const float*)d_in[1];
    const float* W1s = (const float*)d_in[2];
    const float* b1s = (const float*)d_in[3];
    const float* W2s = (const float*)d_in[4];
    const float* b2s = (const float*)d_in[5];
    const int*   src = (const int*)d_in[6];
    const int*   dst = (const int*)d_in[7];
    float* out = (float*)d_out;

    float* hn;
    float* hbuf0;
    float* hbuf1;
    int*   cnt;
    cudaGetSymbolAddress((void**)&hn, g_hn);
    cudaGetSymbolAddress((void**)&hbuf0, g_h);
    cudaGetSymbolAddress((void**)&cnt, g_count);
    hbuf1 = hbuf0 + (size_t)N_NODES * DIM;

    const int UPD_SMEM = (2 * DIM * DIM + 2 * DIM * SPAD) * (int)sizeof(float);
    cudaFuncSetAttribute(update_kernel, cudaFuncAttributeMaxDynamicSharedMemorySize, UPD_SMEM);

    // out[:, 0:64] = x
    {
        int n4 = N_NODES * (DIM / 4);
        copy_x_kernel<<<(n4 + 255) / 256, 256>>>((const float4*)x, (float4*)out);
    }

    // ---- One-time counting sort of edges by dst ----
    zero_kernel<<<128, 256>>>((float4*)cnt, N_NODES / 4);
    hist_kernel<<<(N_EDGES + 255) / 256, 256>>>(dst);
    scan_sum_kernel<<<SCAN_NBLK, SCAN_B>>>();
    scan_tops_kernel<<<1, 128>>>();
    scan_write_kernel<<<SCAN_NBLK, SCAN_B>>>();
    reorder_kernel<<<(N_EDGES + 255) / 256, 256>>>(src, dst, a);

    // ---- Layers ----
    const float* hin = x;
    float* houts[3] = {hbuf0, hbuf1, hbuf0};

    int hw_total = N_EDGES / CHUNK;                     // 50000 half-warps
    int agg_blocks = (hw_total * 16 + 255) / 256;       // 3125 blocks

    for (int l = 0; l < N_LAYERS; l++) {
        zero_kernel<<<2048, 256>>>((float4*)hn, N_NODES * DIM / 4);
        agg_kernel<<<agg_blocks, 256>>>((const float4*)hin, (float4*)hn);
        update_kernel<<<(N_NODES + 63) / 64, 256, UPD_SMEM>>>(
            hin, hn,
            W1s + (size_t)l * DIM * DIM, b1s + (size_t)l * DIM,
            W2s + (size_t)l * DIM * DIM, b2s + (size_t)l * DIM,
            houts[l], out + (size_t)(l + 1) * DIM);
        hin = houts[l];
    }
}

// round 4
// speedup vs baseline: 2.2403x; 1.0891x over previous
#include <cuda_runtime.h>
#include <cuda_bf16.h>

#define N_NODES 100000
#define N_EDGES 3200000
#define DIM 64
#define N_LAYERS 3
#define OUT_DIM (4 * DIM)

#define SCAN_B 1024
#define SCAN_NBLK ((N_NODES + SCAN_B - 1) / SCAN_B)   // 98
#define SPAD 68

// ---------------------------------------------------------------------------
// Scratch (allocation-free contract: __device__ globals)
// ---------------------------------------------------------------------------
__device__ int  g_count[N_NODES];            // per-dst degree histogram
__device__ int  g_cursor[N_NODES];           // running cursors for reorder
__device__ int  g_rowptr[N_NODES + 1];       // CSR offsets (dst-sorted)
__device__ int  g_blocksums[128];            // scan block sums
__device__ int2 g_sorted[N_EDGES];           // packed {src, a_bits}, dst-sorted

// ---------------------------------------------------------------------------
// Generic zero (float4-vectorized, grid-stride)
// ---------------------------------------------------------------------------
__global__ void zero_kernel(float4* __restrict__ p, int n4) {
    int i = blockIdx.x * blockDim.x + threadIdx.x;
    const float4 z = make_float4(0.f, 0.f, 0.f, 0.f);
    for (; i < n4; i += gridDim.x * blockDim.x) p[i] = z;
}

// ---------------------------------------------------------------------------
// Copy x into out[:, 0:64]
// ---------------------------------------------------------------------------
__global__ void copy_x_kernel(const float4* __restrict__ x4, float4* __restrict__ out4) {
    int i = blockIdx.x * blockDim.x + threadIdx.x;
    if (i >= N_NODES * (DIM / 4)) return;
    int n = i >> 4;
    int c = i & 15;
    out4[n * (OUT_DIM / 4) + c] = x4[i];
}

// ---------------------------------------------------------------------------
// Counting sort by dst
// ---------------------------------------------------------------------------
__global__ void hist_kernel(const int* __restrict__ dst) {
    int e = blockIdx.x * blockDim.x + threadIdx.x;
    if (e >= N_EDGES) return;
    atomicAdd(&g_count[dst[e]], 1);
}

__global__ __launch_bounds__(SCAN_B)
void scan_sum_kernel() {
    int i = blockIdx.x * SCAN_B + threadIdx.x;
    int v = (i < N_NODES) ? g_count[i] : 0;
    int lane = threadIdx.x & 31, w = threadIdx.x >> 5;
    #pragma unroll
    for (int d = 16; d; d >>= 1) v += __shfl_down_sync(~0u, v, d);
    __shared__ int s[32];
    if (lane == 0) s[w] = v;
    __syncthreads();
    if (w == 0) {
        v = s[lane];
        #pragma unroll
        for (int d = 16; d; d >>= 1) v += __shfl_down_sync(~0u, v, d);
        if (lane == 0) g_blocksums[blockIdx.x] = v;
    }
}

__global__ void scan_tops_kernel() {
    __shared__ int s[128];
    int tid = threadIdx.x;
    int v = (tid < SCAN_NBLK) ? g_blocksums[tid] : 0;
    s[tid] = v;
    __syncthreads();
    for (int off = 1; off < 128; off <<= 1) {
        int t = (tid >= off) ? s[tid - off] : 0;
        __syncthreads();
        s[tid] += t;
        __syncthreads();
    }
    if (tid < SCAN_NBLK) g_blocksums[tid] = s[tid] - v;   // exclusive
    if (tid == 0) g_rowptr[N_NODES] = N_EDGES;
}

__global__ __launch_bounds__(SCAN_B)
void scan_write_kernel() {
    int i = blockIdx.x * SCAN_B + threadIdx.x;
    int v = (i < N_NODES) ? g_count[i] : 0;
    int lane = threadIdx.x & 31, w = threadIdx.x >> 5;
    int inc = v;
    #pragma unroll
    for (int d = 1; d < 32; d <<= 1) {
        int t = __shfl_up_sync(~0u, inc, d);
        if (lane >= d) inc += t;
    }
    __shared__ int ws[32];
    if (lane == 31) ws[w] = inc;
    __syncthreads();
    if (w == 0) {
        int t = ws[lane];
        #pragma unroll
        for (int d = 1; d < 32; d <<= 1) {
            int u = __shfl_up_sync(~0u, t, d);
            if (lane >= d) t += u;
        }
        ws[lane] = t;
    }
    __syncthreads();
    int warpOff = (w == 0) ? 0 : ws[w - 1];
    int excl = inc - v + warpOff + g_blocksums[blockIdx.x];
    if (i < N_NODES) { g_cursor[i] = excl; g_rowptr[i] = excl; }
}

__global__ void reorder_kernel(const int* __restrict__ src,
                               const int* __restrict__ dst,
                               const float* __restrict__ a) {
    int e = blockIdx.x * blockDim.x + threadIdx.x;
    if (e >= N_EDGES) return;
    int d = dst[e];
    int pos = atomicAdd(&g_cursor[d], 1);
    int2 rec;
    rec.x = src[e];
    rec.y = __float_as_int(a[e]);
    g_sorted[pos] = rec;
}

// ---------------------------------------------------------------------------
// Fused layer kernel:
//   per block: own 64 dst nodes; 16 half-warps each gather+accumulate
//   4 nodes' edge segments (register h_n, no atomics), stage s/p transposed
//   in shared, then register-tiled dual GEMM + bias + lrelu + sum.
//   Reads h in-place from the output tensor (stride strideF4 float4s/row),
//   writes only the layer's 64-col output segment.
// ---------------------------------------------------------------------------
__device__ __forceinline__ float lrelu(float v) {
    return v > 0.f ? v : 0.01f * v;
}

extern __shared__ float dyn_smem[];

__global__ __launch_bounds__(256)
void fused_layer_kernel(const float4* __restrict__ hin, int strideF4,
                        const float* __restrict__ W1, const float* __restrict__ b1,
                        const float* __restrict__ W2, const float* __restrict__ b2,
                        float* __restrict__ outSeg) {
    float* sW1 = dyn_smem;                 // [64*64]
    float* sW2 = sW1 + DIM * DIM;          // [64*64]
    float* sS  = sW2 + DIM * DIM;          // [64][SPAD] k-major
    float* sP  = sS + DIM * SPAD;          // [64][SPAD]

    int t = threadIdx.x;

    // Weights -> shared
    {
        const float4* w1v = (const float4*)W1;
        const float4* w2v = (const float4*)W2;
        float4* s1v = (float4*)sW1;
        float4* s2v = (float4*)sW2;
        #pragma unroll
        for (int i = 0; i < 4; i++) {
            s1v[t + i * 256] = w1v[t + i * 256];
            s2v[t + i * 256] = w2v[t + i * 256];
        }
    }

    int base = blockIdx.x * 64;
    int hw = t >> 4;        // half-warp id 0..15
    int lane = t & 15;      // float4-column within a 64-float row
    int k0 = lane * 4;

    // Gather + accumulate + stage. Each half-warp owns 4 consecutive nodes.
    #pragma unroll
    for (int i = 0; i < 4; i++) {
        int nloc = hw * 4 + i;
        int node = base + nloc;
        float4 acc = make_float4(0.f, 0.f, 0.f, 0.f);
        float4 hv  = make_float4(0.f, 0.f, 0.f, 0.f);
        if (node < N_NODES) {
            int e  = g_rowptr[node];
            int e1 = g_rowptr[node + 1];
            // unrolled by 2: two independent gathers in flight
            for (; e + 1 < e1; e += 2) {
                int2 r0 = g_sorted[e];
                int2 r1 = g_sorted[e + 1];
                float4 v0 = hin[(size_t)r0.x * strideF4 + lane];
                float4 v1 = hin[(size_t)r1.x * strideF4 + lane];
                float a0 = __int_as_float(r0.y);
                float a1 = __int_as_float(r1.y);
                acc.x = fmaf(a0, v0.x, acc.x);
                acc.y = fmaf(a0, v0.y, acc.y);
                acc.z = fmaf(a0, v0.z, acc.z);
                acc.w = fmaf(a0, v0.w, acc.w);
                acc.x = fmaf(a1, v1.x, acc.x);
                acc.y = fmaf(a1, v1.y, acc.y);
                acc.z = fmaf(a1, v1.z, acc.z);
                acc.w = fmaf(a1, v1.w, acc.w);
            }
            if (e < e1) {
                int2 r0 = g_sorted[e];
                float4 v0 = hin[(size_t)r0.x * strideF4 + lane];
                float a0 = __int_as_float(r0.y);
                acc.x = fmaf(a0, v0.x, acc.x);
                acc.y = fmaf(a0, v0.y, acc.y);
                acc.z = fmaf(a0, v0.z, acc.z);
                acc.w = fmaf(a0, v0.w, acc.w);
            }
            hv = hin[(size_t)node * strideF4 + lane];
        }
        // stage s = h + hn, p = h * hn, transposed [k][node]
        sS[(k0 + 0) * SPAD + nloc] = hv.x + acc.x;
        sS[(k0 + 1) * SPAD + nloc] = hv.y + acc.y;
        sS[(k0 + 2) * SPAD + nloc] = hv.z + acc.z;
        sS[(k0 + 3) * SPAD + nloc] = hv.w + acc.w;
        sP[(k0 + 0) * SPAD + nloc] = hv.x * acc.x;
        sP[(k0 + 1) * SPAD + nloc] = hv.y * acc.y;
        sP[(k0 + 2) * SPAD + nloc] = hv.z * acc.z;
        sP[(k0 + 3) * SPAD + nloc] = hv.w * acc.w;
    }
    __syncthreads();

    // Register-tiled dual GEMM: 4 nodes x 4 cols per thread
    int m0 = (t & 15) * 4;
    int c0 = (t >> 4) * 4;

    float acc1[4][4];
    float acc2[4][4];
    #pragma unroll
    for (int i = 0; i < 4; i++)
        #pragma unroll
        for (int j = 0; j < 4; j++) { acc1[i][j] = 0.f; acc2[i][j] = 0.f; }

    #pragma unroll 4
    for (int k = 0; k < DIM; k++) {
        float4 sv = *(const float4*)(sS + k * SPAD + m0);
        float4 pv = *(const float4*)(sP + k * SPAD + m0);
        float4 w1 = *(const float4*)(sW1 + k * DIM + c0);
        float4 w2 = *(const float4*)(sW2 + k * DIM + c0);
        float sm[4] = {sv.x, sv.y, sv.z, sv.w};
        float pm[4] = {pv.x, pv.y, pv.z, pv.w};
        float w1a[4] = {w1.x, w1.y, w1.z, w1.w};
        float w2a[4] = {w2.x, w2.y, w2.z, w2.w};
        #pragma unroll
        for (int i = 0; i < 4; i++) {
            #pragma unroll
            for (int j = 0; j < 4; j++) {
                acc1[i][j] = fmaf(sm[i], w1a[j], acc1[i][j]);
                acc2[i][j] = fmaf(pm[i], w2a[j], acc2[i][j]);
            }
        }
    }

    float4 rb1 = *(const float4*)(b1 + c0);
    float4 rb2 = *(const float4*)(b2 + c0);
    float b1a[4] = {rb1.x, rb1.y, rb1.z, rb1.w};
    float b2a[4] = {rb2.x, rb2.y, rb2.z, rb2.w};

    #pragma unroll
    for (int i = 0; i < 4; i++) {
        int node = base + m0 + i;
        if (node >= N_NODES) break;
        float4 r;
        float* rp = (float*)&r;
        #pragma unroll
        for (int j = 0; j < 4; j++)
            rp[j] = lrelu(acc1[i][j] + b1a[j]) + lrelu(acc2[i][j] + b2a[j]);
        *(float4*)(outSeg + (size_t)node * OUT_DIM + c0) = r;
    }
}

// ---------------------------------------------------------------------------
// Launch
// ---------------------------------------------------------------------------
extern "C" void kernel_launch(void* const* d_in, const int* in_sizes, int n_in,
                              void* d_out, int out_size) {
    const float* x   = (const float*)d_in[0];
    const float* a   = (const float*)d_in[1];
    const float* W1s = (const float*)d_in[2];
    const float* b1s = (const float*)d_in[3];
    const float* W2s = (const float*)d_in[4];
    const float* b2s = (const float*)d_in[5];
    const int*   src = (const int*)d_in[6];
    const int*   dst = (const int*)d_in[7];
    float* out = (float*)d_out;

    int* cnt;
    cudaGetSymbolAddress((void**)&cnt, g_count);

    const int UPD_SMEM = (2 * DIM * DIM + 2 * DIM * SPAD) * (int)sizeof(float); // 67584
    cudaFuncSetAttribute(fused_layer_kernel, cudaFuncAttributeMaxDynamicSharedMemorySize, UPD_SMEM);

    // out[:, 0:64] = x
    {
        int n4 = N_NODES * (DIM / 4);
        copy_x_kernel<<<(n4 + 255) / 256, 256>>>((const float4*)x, (float4*)out);
    }

    // ---- One-time counting sort of edges by dst (CSR + packed records) ----
    zero_kernel<<<128, 256>>>((float4*)cnt, N_NODES / 4);
    hist_kernel<<<(N_EDGES + 255) / 256, 256>>>(dst);
    scan_sum_kernel<<<SCAN_NBLK, SCAN_B>>>();
    scan_tops_kernel<<<1, 128>>>();
    scan_write_kernel<<<SCAN_NBLK, SCAN_B>>>();
    reorder_kernel<<<(N_EDGES + 255) / 256, 256>>>(src, dst, a);

    // ---- Layers: fully fused, h read in-place from output tensor ----
    int grid = (N_NODES + 63) / 64;
    for (int l = 0; l < N_LAYERS; l++) {
        const float4* hin;
        int strideF4;
        if (l == 0) { hin = (const float4*)x; strideF4 = DIM / 4; }
        else        { hin = (const float4*)out + (size_t)l * (DIM / 4); strideF4 = OUT_DIM / 4; }
        fused_layer_kernel<<<grid, 256, UPD_SMEM>>>(
            hin, strideF4,
            W1s + (size_t)l * DIM * DIM, b1s + (size_t)l * DIM,
            W2s + (size_t)l * DIM * DIM, b2s + (size_t)l * DIM,
            out + (size_t)(l + 1) * DIM);
    }
}